// round 1
// baseline (speedup 1.0000x reference)
#include <cuda_runtime.h>
#include <math_constants.h>

// ---------------- problem constants ----------------
#define BATCH   512
#define CWDIM   4096
#define CDIM    64
#define EDIM    64
#define SDIM    1024

// output packing (float32, tuple order)
#define LEN_RECON (512*4096)          // 2,097,152
#define LEN_DIST  (512*64*1024)       // 33,554,432
#define LEN_IDX   (512*64)            // 32,768
#define LEN_MU    (512*256)
#define LEN_LV    (512*256)
#define LEN_DMU   (512*768)
#define LEN_DLV   (512*768)
#define LEN_PLV   (512*768)

#define OFF_RECON 0
#define OFF_DIST  (OFF_RECON + LEN_RECON)
#define OFF_IDX   (OFF_DIST  + LEN_DIST)
#define OFF_MU    (OFF_IDX   + LEN_IDX)
#define OFF_LV    (OFF_MU    + LEN_MU)
#define OFF_DMU   (OFF_LV    + LEN_LV)
#define OFF_DLV   (OFF_DMU   + LEN_DMU)
#define OFF_PLV   (OFF_DLV   + LEN_DLV)

// ---------------- scratch (no allocation allowed) ----------------
__device__ float g_feat[32768 * 512];      // (B*C, ENC_H) post-lrelu   64 MB
__device__ float g_hmax[512 * 512];
__device__ float g_h2[512 * 2048];
__device__ float g_h3[512 * 512];
__device__ float g_t[512 * 2048];          // reused: prior-h, inf2-h, dec-h
__device__ float g_p[512 * 1536];
__device__ float g_cat[512 * 2304];
__device__ float g_d[512 * 1536];
__device__ float g_z2[512 * 768];
__device__ float g_xr2[512 * 64];
__device__ float g_book2[64 * 1024];
__device__ unsigned long long g_keys[512 * 64];

// ---------------- generic tiled fp32 GEMM:  C = act(A @ W^T + bias) ----------------
// A: M x K, row stride lda.  W: N x K row-major.  C: M x N contiguous.
// M % 64 == 0, N % 64 == 0, K % 16 == 0 (true for all call sites here).
#define BM 64
#define BN 64
#define BK 16
__global__ __launch_bounds__(256) void k_gemm(
    const float* __restrict__ A, int lda,
    const float* __restrict__ W,
    const float* __restrict__ bias,
    float* __restrict__ C, int N, int K, int act)
{
    __shared__ float As[BK][BM + 1];
    __shared__ float Ws[BK][BN + 1];
    const int tid = threadIdx.x;
    const int tx = tid & 15, ty = tid >> 4;
    const int bm = blockIdx.y * BM;
    const int bn = blockIdx.x * BN;

    float acc[4][4] = {};

    for (int k0 = 0; k0 < K; k0 += BK) {
#pragma unroll
        for (int i = 0; i < 4; i++) {
            int idx = tid + i * 256;
            int m = idx >> 4, k = idx & 15;
            As[k][m] = A[(size_t)(bm + m) * lda + k0 + k];
            Ws[k][m] = W[(size_t)(bn + m) * K + k0 + k];
        }
        __syncthreads();
#pragma unroll
        for (int k = 0; k < BK; k++) {
            float a[4], w[4];
#pragma unroll
            for (int i = 0; i < 4; i++) a[i] = As[k][ty * 4 + i];
#pragma unroll
            for (int j = 0; j < 4; j++) w[j] = Ws[k][tx * 4 + j];
#pragma unroll
            for (int i = 0; i < 4; i++)
#pragma unroll
                for (int j = 0; j < 4; j++)
                    acc[i][j] = fmaf(a[i], w[j], acc[i][j]);
        }
        __syncthreads();
    }

#pragma unroll
    for (int i = 0; i < 4; i++) {
        int m = bm + ty * 4 + i;
        float4 v;
        float* vp = reinterpret_cast<float*>(&v);
#pragma unroll
        for (int j = 0; j < 4; j++) {
            int n = bn + tx * 4 + j;
            float r = acc[i][j] + __ldg(&bias[n]);
            if (act) r = r > 0.f ? r : 0.2f * r;
            vp[j] = r;
        }
        *reinterpret_cast<float4*>(&C[(size_t)m * N + bn + tx * 4]) = v;
    }
}

// ---------------- max-pool over codes: hmax[b,h] = max_c feat[(b*64+c), h] ----------------
__global__ void k_maxpool(const float* __restrict__ feat, float* __restrict__ hmax)
{
    int idx = blockIdx.x * blockDim.x + threadIdx.x;   // b*512 + h
    int b = idx >> 9, h = idx & 511;
    float m = -CUDART_INF_F;
#pragma unroll 8
    for (int c = 0; c < 64; c++)
        m = fmaxf(m, feat[(((size_t)b * 64 + c) << 9) + h]);
    hmax[idx] = m;
}

// ---------------- copy a column slice: dst[b, 0:n] = src[b, col0:col0+n] ----------------
__global__ void k_copyslice(const float* __restrict__ src, int ld, int col0, int ncols,
                            float* __restrict__ dst, int total)
{
    int idx = blockIdx.x * blockDim.x + threadIdx.x;
    if (idx >= total) return;
    int b = idx / ncols, j = idx - b * ncols;
    dst[idx] = src[(size_t)b * ld + col0 + j];
}

// ---------------- concat [z1 (256) | h (2048)] -> (B, 2304) ----------------
__global__ void k_cat(const float* __restrict__ z1 /*g_h3, ld 512*/,
                      const float* __restrict__ h  /*g_h2, ld 2048*/,
                      float* __restrict__ dst)
{
    int idx = blockIdx.x * blockDim.x + threadIdx.x;
    if (idx >= 512 * 2304) return;
    int b = idx / 2304, j = idx - b * 2304;
    dst[idx] = (j < 256) ? z1[(size_t)b * 512 + j] : h[(size_t)b * 2048 + (j - 256)];
}

// ---------------- z2 = d_mu + p_mu, and init argmin keys ----------------
__global__ void k_z2(const float* __restrict__ d, const float* __restrict__ p,
                     float* __restrict__ z2)
{
    int idx = blockIdx.x * blockDim.x + threadIdx.x;
    if (idx >= 512 * 768) return;
    int b = idx / 768, j = idx - b * 768;
    z2[idx] = d[(size_t)b * 1536 + j] + p[(size_t)b * 1536 + j];
}

__global__ void k_initkeys(unsigned long long* __restrict__ keys)
{
    int idx = blockIdx.x * blockDim.x + threadIdx.x;
    if (idx < 512 * 64) keys[idx] = ~0ull;
}

// ---------------- squared row norms (rows of length 64) ----------------
__global__ void k_rowsq(const float* __restrict__ src, float* __restrict__ dst, int nrows)
{
    int idx = blockIdx.x * blockDim.x + threadIdx.x;
    if (idx >= nrows) return;
    const float4* p = reinterpret_cast<const float4*>(src + (size_t)idx * 64);
    float s = 0.f;
#pragma unroll
    for (int i = 0; i < 16; i++) {
        float4 v = p[i];
        s += v.x * v.x + v.y * v.y + v.z * v.z + v.w * v.w;
    }
    dst[idx] = s;
}

// ---------------- dist + fused argmin ----------------
// dist[b,c,s] = xr2[b,c] + book2[c,s] - 2 * sum_e xr[b,c,e]*book[c,s,e]
// grid: (SDIM/64, BATCH/64, CDIM), block 256 (16x16, 4x4 per thread)
__device__ __forceinline__ unsigned int f32_ordered(float f)
{
    unsigned int b = __float_as_uint(f);
    return (b & 0x80000000u) ? ~b : (b | 0x80000000u);
}

__global__ __launch_bounds__(256) void k_dist(
    const float* __restrict__ recon,
    const float* __restrict__ book,
    const float* __restrict__ xr2,
    const float* __restrict__ book2,
    float* __restrict__ dist,
    unsigned long long* __restrict__ keys)
{
    __shared__ float As[64][65];   // [e][b]
    __shared__ float Ws[64][65];   // [e][s]
    const int tid = threadIdx.x;
    const int tx = tid & 15, ty = tid >> 4;
    const int c  = blockIdx.z;
    const int bm = blockIdx.y * 64;
    const int sn = blockIdx.x * 64;

#pragma unroll
    for (int i = 0; i < 16; i++) {
        int idx = tid + i * 256;
        int m = idx >> 6, e = idx & 63;
        As[e][m] = recon[(size_t)(bm + m) * 4096 + c * 64 + e];
        Ws[e][m] = book[((size_t)c * 1024 + sn + m) * 64 + e];
    }
    __syncthreads();

    float acc[4][4] = {};
#pragma unroll 16
    for (int e = 0; e < 64; e++) {
        float a[4], w[4];
#pragma unroll
        for (int i = 0; i < 4; i++) a[i] = As[e][ty * 4 + i];
#pragma unroll
        for (int j = 0; j < 4; j++) w[j] = Ws[e][tx * 4 + j];
#pragma unroll
        for (int i = 0; i < 4; i++)
#pragma unroll
            for (int j = 0; j < 4; j++)
                acc[i][j] = fmaf(a[i], w[j], acc[i][j]);
    }

#pragma unroll
    for (int i = 0; i < 4; i++) {
        int b = bm + ty * 4 + i;
        float x2 = xr2[b * 64 + c];
        float4 v;
        float* vp = reinterpret_cast<float*>(&v);
        unsigned long long kbest = ~0ull;
#pragma unroll
        for (int j = 0; j < 4; j++) {
            int s = sn + tx * 4 + j;
            float dval = x2 + __ldg(&book2[c * 1024 + s]) - 2.f * acc[i][j];
            vp[j] = dval;
            unsigned long long key = ((unsigned long long)f32_ordered(dval) << 32) |
                                     (unsigned int)s;
            kbest = min(kbest, key);
        }
        *reinterpret_cast<float4*>(&dist[((size_t)b * 64 + c) * 1024 + sn + tx * 4]) = v;
#pragma unroll
        for (int off = 8; off; off >>= 1) {
            unsigned long long o = __shfl_xor_sync(0xffffffffu, kbest, off, 16);
            kbest = min(kbest, o);
        }
        if (tx == 0) atomicMin(&keys[b * 64 + c], kbest);
    }
}

__global__ void k_writeidx(const unsigned long long* __restrict__ keys,
                           float* __restrict__ out)
{
    int idx = blockIdx.x * blockDim.x + threadIdx.x;
    if (idx < 512 * 64)
        out[idx] = (float)(unsigned int)(keys[idx] & 0xFFFFFFFFull);
}

// ---------------- launcher ----------------
extern "C" void kernel_launch(void* const* d_in, const int* in_sizes, int n_in,
                              void* d_out, int out_size)
{
    const float* x        = (const float*)d_in[0];
    const float* codebook = (const float*)d_in[1];
    const float* enc_w1   = (const float*)d_in[2];
    const float* enc_b1   = (const float*)d_in[3];
    const float* enc_w2   = (const float*)d_in[4];
    const float* enc_b2   = (const float*)d_in[5];
    const float* inf1_w   = (const float*)d_in[6];
    const float* inf1_b   = (const float*)d_in[7];
    const float* inf2_w1  = (const float*)d_in[8];
    const float* inf2_b1  = (const float*)d_in[9];
    const float* inf2_w2  = (const float*)d_in[10];
    const float* inf2_b2  = (const float*)d_in[11];
    const float* prior_w1 = (const float*)d_in[12];
    const float* prior_b1 = (const float*)d_in[13];
    const float* prior_w2 = (const float*)d_in[14];
    const float* prior_b2 = (const float*)d_in[15];
    const float* dec_w1   = (const float*)d_in[16];
    const float* dec_b1   = (const float*)d_in[17];
    const float* dec_w2   = (const float*)d_in[18];
    const float* dec_b2   = (const float*)d_in[19];
    float* out = (float*)d_out;

    float *feat, *hmax, *h2, *h3, *t, *p, *cat, *d, *z2, *xr2, *book2;
    unsigned long long* keys;
    cudaGetSymbolAddress((void**)&feat,  g_feat);
    cudaGetSymbolAddress((void**)&hmax,  g_hmax);
    cudaGetSymbolAddress((void**)&h2,    g_h2);
    cudaGetSymbolAddress((void**)&h3,    g_h3);
    cudaGetSymbolAddress((void**)&t,     g_t);
    cudaGetSymbolAddress((void**)&p,     g_p);
    cudaGetSymbolAddress((void**)&cat,   g_cat);
    cudaGetSymbolAddress((void**)&d,     g_d);
    cudaGetSymbolAddress((void**)&z2,    g_z2);
    cudaGetSymbolAddress((void**)&xr2,   g_xr2);
    cudaGetSymbolAddress((void**)&book2, g_book2);
    cudaGetSymbolAddress((void**)&keys,  g_keys);

    // 1) encoder conv: feat = lrelu(x(32768,64) @ enc_w1^T + b1)  -> (32768, 512)
    k_gemm<<<dim3(512 / BN, 32768 / BM), 256>>>(x, 64, enc_w1, enc_b1, feat, 512, 64, 1);
    // 2) max-pool over codes -> hmax (512, 512)
    k_maxpool<<<(512 * 512) / 256, 256>>>(feat, hmax);
    // 3) h2 = hmax @ enc_w2^T + b2  -> (512, 2048)
    k_gemm<<<dim3(2048 / BN, 512 / BM), 256>>>(hmax, 512, enc_w2, enc_b2, h2, 2048, 512, 0);
    // 4) h3 = h2 @ inf1_w^T + inf1_b -> (512, 512); mu = h3[:, :256], lv = h3[:, 256:]
    k_gemm<<<dim3(512 / BN, 512 / BM), 256>>>(h2, 2048, inf1_w, inf1_b, h3, 512, 2048, 0);
    k_copyslice<<<(512 * 256 + 255) / 256, 256>>>(h3, 512, 0,   256, out + OFF_MU, 512 * 256);
    k_copyslice<<<(512 * 256 + 255) / 256, 256>>>(h3, 512, 256, 256, out + OFF_LV, 512 * 256);
    // 5) prior: t = lrelu(z1 @ prior_w1^T + b); p = t @ prior_w2^T + b -> (512, 1536)
    k_gemm<<<dim3(2048 / BN, 512 / BM), 256>>>(h3, 512, prior_w1, prior_b1, t, 2048, 256, 1);
    k_gemm<<<dim3(1536 / BN, 512 / BM), 256>>>(t, 2048, prior_w2, prior_b2, p, 1536, 2048, 0);
    k_copyslice<<<(512 * 768 + 255) / 256, 256>>>(p, 1536, 768, 768, out + OFF_PLV, 512 * 768);
    // 6) inf2: cat = [z1 | h2] (512, 2304); t = lrelu(cat @ w1^T + b); d = t @ w2^T + b
    k_cat<<<(512 * 2304 + 255) / 256, 256>>>(h3, h2, cat);
    k_gemm<<<dim3(2048 / BN, 512 / BM), 256>>>(cat, 2304, inf2_w1, inf2_b1, t, 2048, 2304, 1);
    k_gemm<<<dim3(1536 / BN, 512 / BM), 256>>>(t, 2048, inf2_w2, inf2_b2, d, 1536, 2048, 0);
    k_copyslice<<<(512 * 768 + 255) / 256, 256>>>(d, 1536, 0,   768, out + OFF_DMU, 512 * 768);
    k_copyslice<<<(512 * 768 + 255) / 256, 256>>>(d, 1536, 768, 768, out + OFF_DLV, 512 * 768);
    // 7) z2 = d_mu + p_mu
    k_z2<<<(512 * 768 + 255) / 256, 256>>>(d, p, z2);
    // 8) decoder: t = lrelu(z2 @ dec_w1^T + b); cw_recon = t @ dec_w2^T + b -> out
    k_gemm<<<dim3(2048 / BN, 512 / BM), 256>>>(z2, 768, dec_w1, dec_b1, t, 2048, 768, 1);
    k_gemm<<<dim3(4096 / BN, 512 / BM), 256>>>(t, 2048, dec_w2, dec_b2, out + OFF_RECON, 4096, 2048, 0);
    // 9) dist + argmin
    k_rowsq<<<(512 * 64 + 255) / 256, 256>>>(out + OFF_RECON, xr2, 512 * 64);
    k_rowsq<<<(64 * 1024 + 255) / 256, 256>>>(codebook, book2, 64 * 1024);
    k_initkeys<<<(512 * 64 + 255) / 256, 256>>>(keys);
    k_dist<<<dim3(1024 / 64, 512 / 64, 64), 256>>>(out + OFF_RECON, codebook, xr2, book2,
                                                   out + OFF_DIST, keys);
    k_writeidx<<<(512 * 64 + 255) / 256, 256>>>(keys, out + OFF_IDX);
}